// round 16
// baseline (speedup 1.0000x reference)
#include <cuda_runtime.h>
#include <math.h>
#include <stdint.h>

// ---------------- problem constants ----------------
#define W     8192      // words
#define LC    16        // chars per word (padded)
#define CD    100       // char emb dim
#define CDP   128       // padded to %32 for tensor GEMM
#define WD    300       // word emb dim
#define HD    512       // hidden dim (bi)
#define HH    256       // per-direction hidden
#define G4    1024      // 4*HH gates
#define WDIN  812       // WD + HD
#define WDINP 832       // padded to %32
#define T1    48
#define T2    32

#define CLUST    8      // word-lstm CTAs per direction (one cluster)
#define CELLS    32     // cells per CTA

#define ALN __align__(16)

// smem layout constants for GEMM (floats)
#define KCH   32
#define RPAD  36
#define ABUF  (128 * RPAD)
#define BUFSZ (2 * ABUF)
#define GEMM_SMEM_BYTES (2 * BUFSZ * 4)   // 73728 B

// ---------------- static device scratch (no cudaMalloc allowed) ----------------
__device__ ALN float g_Xc[(size_t)LC * W * CDP];
__device__ ALN float g_XGf[(size_t)LC * W * G4];      // char input gates (PERMUTED cols), fwd
__device__ ALN float g_XGb[(size_t)LC * W * G4];      // char input gates (PERMUTED cols), bwd
__device__ ALN float g_Hst[2][2][(size_t)W * HH];     // [dir][parity] h double buffer
__device__ ALN float g_Cst[2][(size_t)W * HH];        // [dir] c state (in-place)
__device__ ALN float g_WX[(size_t)W * WDINP];
__device__ ALN float g_XGw[(size_t)2 * W * G4];
__device__ ALN float g_OUT[(size_t)W * HD];
__device__ ALN float g_WihC[2][G4 * CDP];             // permuted rows
__device__ ALN float g_WhhC[2][G4 * HH];              // permuted rows
__device__ ALN float g_WihW[2][G4 * WDINP];           // standard rows
__device__ ALN float g_bias[4][G4];                   // [0,1]=char permuted; [2,3]=word std

__device__ __forceinline__ float fast_sigmoid(float x) {
    return __fdividef(1.0f, 1.0f + __expf(-x));
}
__device__ __forceinline__ float fast_tanh(float x) {
    return 1.0f - __fdividef(2.0f, __expf(2.0f * x) + 1.0f);
}

__device__ __forceinline__ uint32_t smem_u32(const void* p) {
    uint32_t a;
    asm("{ .reg .u64 t; cvta.to.shared.u64 t, %1; cvt.u32.u64 %0, t; }" : "=r"(a) : "l"(p));
    return a;
}
__device__ __forceinline__ uint32_t to_tf32(float x) {
    uint32_t u;
    asm("cvt.rna.tf32.f32 %0, %1;" : "=r"(u) : "f"(x));
    return u;
}
#define CP_ASYNC16(dst, src) \
    asm volatile("cp.async.cg.shared.global [%0], [%1], 16;" :: "r"(dst), "l"(src) : "memory")
#define CP_COMMIT()  asm volatile("cp.async.commit_group;" ::: "memory")
#define CP_WAIT(n)   asm volatile("cp.async.wait_group %0;" :: "n"(n) : "memory")

// cluster barrier (split) and DSMEM store
#define CLUSTER_ARRIVE() asm volatile("barrier.cluster.arrive.aligned;" ::: "memory")
#define CLUSTER_WAIT()   asm volatile("barrier.cluster.wait.aligned;" ::: "memory")
#define ST_CLUSTER_F32(local_addr, rank, val)                                         \
    asm volatile("{\n\t.reg .b32 ra;\n\t"                                             \
                 "mapa.shared::cluster.u32 ra, %0, %1;\n\t"                           \
                 "st.shared::cluster.f32 [ra], %2;\n\t}"                              \
                 :: "r"(local_addr), "r"(rank), "f"(val) : "memory")

// packed fp32x2 helpers
#define PACK_F32X2(out, lo, hi) \
    asm("mov.b64 %0, {%1, %2};" : "=l"(out) : "f"(lo), "f"(hi))
#define UNPACK_F32X2(lo, hi, in) \
    asm("mov.b64 {%0, %1}, %2;" : "=f"(lo), "=f"(hi) : "l"(in))
#define FMA_F32X2(acc, a, b) \
    asm("fma.rn.f32x2 %0, %1, %2, %0;" : "+l"(acc) : "l"(a), "l"(b))

// ---------------- GEMM core macro body pieces (shared by plain + fused kernels) ------------
// (kept as plain code in each kernel for clarity)

// ---------------- TF32 mma.sync dual GEMM (C = A@B^T + bias + D) ----------------
__global__ __launch_bounds__(256, 2)
void gemm_mma_dual_kernel(const float* __restrict__ A0, const float* __restrict__ A1,
                          const float* __restrict__ B0, const float* __restrict__ B1,
                          const float* __restrict__ bias0, const float* __restrict__ bias1,
                          const float* __restrict__ D0, const float* __restrict__ D1,
                          float* __restrict__ C0, float* __restrict__ C1,
                          int N, int K)
{
    extern __shared__ ALN float smem[];

    const int tid = threadIdx.x;
    const int lane = tid & 31, wid = tid >> 5;
    const int wm = wid & 1, wn = wid >> 1;
    const int bx = blockIdx.x, by = blockIdx.y, bz = blockIdx.z;

    const float* A    = bz ? A1 : A0;
    const float* B    = bz ? B1 : B0;
    const float* bias = bz ? bias1 : bias0;
    const float* Dadd = bz ? D1 : D0;
    float*       C    = bz ? C1 : C0;

    const float* Abase = A + (size_t)(by * 128) * K;
    const float* Bbase = B + (size_t)(bx * 128) * K;

    float acc[4][4][4];
#pragma unroll
    for (int i = 0; i < 4; i++)
#pragma unroll
        for (int j = 0; j < 4; j++)
#pragma unroll
            for (int q = 0; q < 4; q++) acc[i][j][q] = 0.0f;

    const int nkt = K >> 5;

    {
        float* dst = smem;
#pragma unroll
        for (int i = 0; i < 4; i++) {
            int f = tid + i * 256;
            int row = f >> 3, c4 = f & 7;
            CP_ASYNC16(smem_u32(dst + row * RPAD + c4 * 4), Abase + (size_t)row * K + c4 * 4);
            CP_ASYNC16(smem_u32(dst + ABUF + row * RPAD + c4 * 4), Bbase + (size_t)row * K + c4 * 4);
        }
        CP_COMMIT();
    }

    for (int kt = 0; kt < nkt; kt++) {
        if (kt + 1 < nkt) {
            float* dst = smem + ((kt + 1) & 1) * BUFSZ;
            const float* Ak = Abase + (kt + 1) * KCH;
            const float* Bk = Bbase + (kt + 1) * KCH;
#pragma unroll
            for (int i = 0; i < 4; i++) {
                int f = tid + i * 256;
                int row = f >> 3, c4 = f & 7;
                CP_ASYNC16(smem_u32(dst + row * RPAD + c4 * 4), Ak + (size_t)row * K + c4 * 4);
                CP_ASYNC16(smem_u32(dst + ABUF + row * RPAD + c4 * 4), Bk + (size_t)row * K + c4 * 4);
            }
            CP_COMMIT();
            CP_WAIT(1);
        } else {
            CP_WAIT(0);
        }
        __syncthreads();

        const float* As = smem + (kt & 1) * BUFSZ;
        const float* Bs = As + ABUF;

#pragma unroll
        for (int kk = 0; kk < 4; kk++) {
            const int k0 = kk * 8 + (lane & 3);
            const int rA = wm * 64 + (lane >> 2);
            uint32_t a[4][4];
#pragma unroll
            for (int ms = 0; ms < 4; ms++) {
                const float* ap = As + (rA + ms * 16) * RPAD + k0;
                a[ms][0] = to_tf32(ap[0]);
                a[ms][1] = to_tf32(ap[8 * RPAD]);
                a[ms][2] = to_tf32(ap[4]);
                a[ms][3] = to_tf32(ap[8 * RPAD + 4]);
            }
            uint32_t b[4][2];
            const int nB = wn * 32 + (lane >> 2);
#pragma unroll
            for (int ns = 0; ns < 4; ns++) {
                const float* bp = Bs + (nB + ns * 8) * RPAD + k0;
                b[ns][0] = to_tf32(bp[0]);
                b[ns][1] = to_tf32(bp[4]);
            }
#pragma unroll
            for (int ms = 0; ms < 4; ms++)
#pragma unroll
                for (int ns = 0; ns < 4; ns++) {
                    asm volatile(
                        "mma.sync.aligned.m16n8k8.row.col.f32.tf32.tf32.f32 "
                        "{%0,%1,%2,%3}, {%4,%5,%6,%7}, {%8,%9}, {%0,%1,%2,%3};"
                        : "+f"(acc[ms][ns][0]), "+f"(acc[ms][ns][1]),
                          "+f"(acc[ms][ns][2]), "+f"(acc[ms][ns][3])
                        : "r"(a[ms][0]), "r"(a[ms][1]), "r"(a[ms][2]), "r"(a[ms][3]),
                          "r"(b[ns][0]), "r"(b[ns][1]));
                }
        }
        __syncthreads();
    }

#pragma unroll
    for (int ms = 0; ms < 4; ms++) {
        int row = by * 128 + wm * 64 + ms * 16 + (lane >> 2);
#pragma unroll
        for (int ns = 0; ns < 4; ns++) {
            int col = bx * 128 + wn * 32 + ns * 8 + (lane & 3) * 2;
            float2 bb = make_float2(0.f, 0.f);
            if (bias) bb = *(const float2*)(bias + col);
            {
                float2 v = make_float2(acc[ms][ns][0] + bb.x, acc[ms][ns][1] + bb.y);
                if (Dadd) {
                    float2 dd = *(const float2*)(Dadd + (size_t)row * N + col);
                    v.x += dd.x; v.y += dd.y;
                }
                *(float2*)(C + (size_t)row * N + col) = v;
            }
            {
                float2 v = make_float2(acc[ms][ns][2] + bb.x, acc[ms][ns][3] + bb.y);
                if (Dadd) {
                    float2 dd = *(const float2*)(Dadd + (size_t)(row + 8) * N + col);
                    v.x += dd.x; v.y += dd.y;
                }
                *(float2*)(C + (size_t)(row + 8) * N + col) = v;
            }
        }
    }
}

// ---------------- FUSED char recurrent GEMM + LSTM gate epilogue ----------------
// Gate-interleaved layout: weight row' = cell*4 + gate, so a 128-col tile = 32 full cells.
// Epilogue: even (lane&3) holds gates (i,f), partner lane (^1) holds (g,o) of the SAME
// cell; one shfl_xor(1) gathers the quad, even lanes apply the masked LSTM cell update.
// H is parity double-buffered (read Hin, write Hout) to avoid read/write races; C in place.
__global__ __launch_bounds__(256, 2)
void gemm_lstm_fused_kernel(const float* __restrict__ Hin0, const float* __restrict__ Hin1,
                            const float* __restrict__ B0, const float* __restrict__ B1,
                            const float* __restrict__ XG0, const float* __restrict__ XG1,
                            float* __restrict__ Hout0, float* __restrict__ Hout1,
                            float* __restrict__ Cst0, float* __restrict__ Cst1,
                            const int* __restrict__ lens, int t0, int t1)
{
    extern __shared__ ALN float smem[];

    const int tid = threadIdx.x;
    const int lane = tid & 31, wid = tid >> 5;
    const int wm = wid & 1, wn = wid >> 1;
    const int bx = blockIdx.x, by = blockIdx.y, bz = blockIdx.z;
    const int N = G4, K = HH;

    const float* A    = bz ? Hin1 : Hin0;
    const float* B    = bz ? B1 : B0;
    const float* Dadd = bz ? XG1 : XG0;
    float*       Hout = bz ? Hout1 : Hout0;
    float*       Cst  = bz ? Cst1 : Cst0;
    const float* Hin  = A;
    const int    tcur = bz ? t1 : t0;

    const float* Abase = A + (size_t)(by * 128) * K;
    const float* Bbase = B + (size_t)(bx * 128) * K;

    float acc[4][4][4];
#pragma unroll
    for (int i = 0; i < 4; i++)
#pragma unroll
        for (int j = 0; j < 4; j++)
#pragma unroll
            for (int q = 0; q < 4; q++) acc[i][j][q] = 0.0f;

    const int nkt = K >> 5;   // 8

    {
        float* dst = smem;
#pragma unroll
        for (int i = 0; i < 4; i++) {
            int f = tid + i * 256;
            int row = f >> 3, c4 = f & 7;
            CP_ASYNC16(smem_u32(dst + row * RPAD + c4 * 4), Abase + (size_t)row * K + c4 * 4);
            CP_ASYNC16(smem_u32(dst + ABUF + row * RPAD + c4 * 4), Bbase + (size_t)row * K + c4 * 4);
        }
        CP_COMMIT();
    }

    for (int kt = 0; kt < nkt; kt++) {
        if (kt + 1 < nkt) {
            float* dst = smem + ((kt + 1) & 1) * BUFSZ;
            const float* Ak = Abase + (kt + 1) * KCH;
            const float* Bk = Bbase + (kt + 1) * KCH;
#pragma unroll
            for (int i = 0; i < 4; i++) {
                int f = tid + i * 256;
                int row = f >> 3, c4 = f & 7;
                CP_ASYNC16(smem_u32(dst + row * RPAD + c4 * 4), Ak + (size_t)row * K + c4 * 4);
                CP_ASYNC16(smem_u32(dst + ABUF + row * RPAD + c4 * 4), Bk + (size_t)row * K + c4 * 4);
            }
            CP_COMMIT();
            CP_WAIT(1);
        } else {
            CP_WAIT(0);
        }
        __syncthreads();

        const float* As = smem + (kt & 1) * BUFSZ;
        const float* Bs = As + ABUF;

#pragma unroll
        for (int kk = 0; kk < 4; kk++) {
            const int k0 = kk * 8 + (lane & 3);
            const int rA = wm * 64 + (lane >> 2);
            uint32_t a[4][4];
#pragma unroll
            for (int ms = 0; ms < 4; ms++) {
                const float* ap = As + (rA + ms * 16) * RPAD + k0;
                a[ms][0] = to_tf32(ap[0]);
                a[ms][1] = to_tf32(ap[8 * RPAD]);
                a[ms][2] = to_tf32(ap[4]);
                a[ms][3] = to_tf32(ap[8 * RPAD + 4]);
            }
            uint32_t b[4][2];
            const int nB = wn * 32 + (lane >> 2);
#pragma unroll
            for (int ns = 0; ns < 4; ns++) {
                const float* bp = Bs + (nB + ns * 8) * RPAD + k0;
                b[ns][0] = to_tf32(bp[0]);
                b[ns][1] = to_tf32(bp[4]);
            }
#pragma unroll
            for (int ms = 0; ms < 4; ms++)
#pragma unroll
                for (int ns = 0; ns < 4; ns++) {
                    asm volatile(
                        "mma.sync.aligned.m16n8k8.row.col.f32.tf32.tf32.f32 "
                        "{%0,%1,%2,%3}, {%4,%5,%6,%7}, {%8,%9}, {%0,%1,%2,%3};"
                        : "+f"(acc[ms][ns][0]), "+f"(acc[ms][ns][1]),
                          "+f"(acc[ms][ns][2]), "+f"(acc[ms][ns][3])
                        : "r"(a[ms][0]), "r"(a[ms][1]), "r"(a[ms][2]), "r"(a[ms][3]),
                          "r"(b[ns][0]), "r"(b[ns][1]));
                }
        }
        __syncthreads();
    }

    // ---- fused LSTM epilogue ----
    const int k = lane & 3;
#pragma unroll
    for (int ms = 0; ms < 4; ms++) {
        int r0 = by * 128 + wm * 64 + ms * 16 + (lane >> 2);
        int r1 = r0 + 8;
        int len0 = lens[r0], len1 = lens[r1];
#pragma unroll
        for (int ns = 0; ns < 4; ns++) {
            int col = bx * 128 + wn * 32 + ns * 8 + k * 2;
            float2 d0 = *(const float2*)(Dadd + (size_t)r0 * N + col);
            float2 d1 = *(const float2*)(Dadd + (size_t)r1 * N + col);
            float a0 = acc[ms][ns][0] + d0.x;   // even k: gate i  | odd k: gate g
            float a1 = acc[ms][ns][1] + d0.y;   // even k: gate f  | odd k: gate o
            float a2 = acc[ms][ns][2] + d1.x;
            float a3 = acc[ms][ns][3] + d1.y;
            float p0 = __shfl_xor_sync(0xFFFFFFFFu, a0, 1);
            float p1 = __shfl_xor_sync(0xFFFFFFFFu, a1, 1);
            float p2 = __shfl_xor_sync(0xFFFFFFFFu, a2, 1);
            float p3 = __shfl_xor_sync(0xFFFFFFFFu, a3, 1);
            if (!(k & 1)) {
                int cell = col >> 2;
                if (tcur < len0) {
                    float co = Cst[(size_t)r0 * HH + cell];
                    float cn = fast_sigmoid(a1) * co + fast_sigmoid(a0) * fast_tanh(p0);
                    float hn = fast_sigmoid(p1) * fast_tanh(cn);
                    Cst[(size_t)r0 * HH + cell] = cn;
                    Hout[(size_t)r0 * HH + cell] = hn;
                } else {
                    Hout[(size_t)r0 * HH + cell] = Hin[(size_t)r0 * HH + cell];
                }
                if (tcur < len1) {
                    float co = Cst[(size_t)r1 * HH + cell];
                    float cn = fast_sigmoid(a3) * co + fast_sigmoid(a2) * fast_tanh(p2);
                    float hn = fast_sigmoid(p3) * fast_tanh(cn);
                    Cst[(size_t)r1 * HH + cell] = cn;
                    Hout[(size_t)r1 * HH + cell] = hn;
                } else {
                    Hout[(size_t)r1 * HH + cell] = Hin[(size_t)r1 * HH + cell];
                }
            }
        }
    }
}

// ---------------- small utility kernels ----------------
__global__ void zero_kernel(float* p, size_t n) {
    size_t i = (size_t)blockIdx.x * blockDim.x + threadIdx.x;
    if (i < n) p[i] = 0.0f;
}

// pack char Wih with row permutation row' = cell*4 + gate, K padded to CDP
__global__ void pack_wihc_perm_kernel(const float* __restrict__ src, float* __restrict__ dst) {
    int n = blockIdx.x;                     // source row: g*256 + j
    int rp = ((n & 255) << 2) | (n >> 8);   // dest row: j*4 + g
    for (int kk = threadIdx.x; kk < CDP; kk += blockDim.x)
        dst[rp * CDP + kk] = (kk < CD) ? src[n * CD + kk] : 0.0f;
}

// pack char Whh with same row permutation (K = 256, no padding)
__global__ void pack_whhc_perm_kernel(const float* __restrict__ src, float* __restrict__ dst) {
    int n = blockIdx.x;
    int rp = ((n & 255) << 2) | (n >> 8);
    for (int kk = threadIdx.x; kk < HH; kk += blockDim.x)
        dst[rp * HH + kk] = src[n * HH + kk];
}

__global__ void pack_wihw_kernel(const float* __restrict__ src, float* __restrict__ dst) {
    int n = blockIdx.x;
    for (int kk = threadIdx.x; kk < WDINP; kk += blockDim.x)
        dst[n * WDINP + kk] = (kk < WDIN) ? src[n * WDIN + kk] : 0.0f;
}

__global__ void bias_sum_perm_kernel(const float* __restrict__ a, const float* __restrict__ b,
                                     float* __restrict__ o) {
    int i = blockIdx.x * blockDim.x + threadIdx.x;
    if (i < G4) o[((i & 255) << 2) | (i >> 8)] = a[i] + b[i];
}

__global__ void bias_sum_kernel(const float* __restrict__ a, const float* __restrict__ b,
                                float* __restrict__ o) {
    int i = blockIdx.x * blockDim.x + threadIdx.x;
    if (i < G4) o[i] = a[i] + b[i];
}

__global__ void gather_char_kernel(const int* __restrict__ cseq, const float* __restrict__ cemb,
                                   float* __restrict__ Xc) {
    int id = blockIdx.x;            // id = t*W + w
    int t = id >> 13;
    int w = id & (W - 1);
    int ci = cseq[w * LC + t];
    float* dst = Xc + (size_t)id * CDP;
    const float* src = cemb + (size_t)ci * CD;
    for (int kk = threadIdx.x; kk < CDP; kk += blockDim.x)
        dst[kk] = (kk < CD) ? src[kk] : 0.0f;
}

__global__ void gather_word_kernel(const int* __restrict__ wseq, const float* __restrict__ wemb,
                                   const float* __restrict__ Hf, const float* __restrict__ Hb,
                                   float* __restrict__ WX) {
    int w = blockIdx.x;
    int wi = wseq[w];
    float* dst = WX + (size_t)w * WDINP;
    for (int kk = threadIdx.x; kk < WDINP; kk += blockDim.x) {
        float v;
        if (kk < WD)            v = wemb[(size_t)wi * WD + kk];
        else if (kk < WD + HH)  v = Hf[(size_t)w * HH + (kk - WD)];
        else if (kk < WDIN)     v = Hb[(size_t)w * HH + (kk - WD - HH)];
        else                    v = 0.0f;
        dst[kk] = v;
    }
}

// ---------------- sequential word BiLSTM: 8-CTA clusters, DSMEM exchange (round-15 WIN) ----
__global__ __launch_bounds__(256, 1) __cluster_dims__(CLUST, 1, 1)
void word_lstm_kernel(const float* __restrict__ XGw,
                      const float* __restrict__ WhhF, const float* __restrict__ WhhB,
                      float* __restrict__ OUT)
{
    const int d = blockIdx.x >> 3;
    const int b = blockIdx.x & 7;
    const int tid = threadIdx.x;
    const int r = tid >> 1;
    const int half = tid & 1;
    const int g = r >> 5, jj = r & 31;
    const int rowg = (g << 8) + b * CELLS + jj;

    const float* Whh = d ? WhhB : WhhF;
    const float* xgbase = XGw + (size_t)d * W * G4;

    __shared__ ALN float h_sh[2][HH];
    __shared__ ALN float gsh[128];

    unsigned long long wpk[64];
#pragma unroll
    for (int i = 0; i < 128; i += 4) {
        float4 v = *(const float4*)(Whh + (size_t)rowg * HH + half * 128 + i);
        PACK_F32X2(wpk[(i >> 1) + 0], v.x, v.y);
        PACK_F32X2(wpk[(i >> 1) + 1], v.z, v.w);
    }
    ((float*)h_sh)[tid] = 0.0f;
    ((float*)h_sh)[tid + 256] = 0.0f;
    float c = 0.0f;
    __syncthreads();
    CLUSTER_ARRIVE();
    CLUSTER_WAIT();

    float xg_cur = 0.0f;
    if (half == 0) xg_cur = __ldg(xgbase + (size_t)(d ? (W - 1) : 0) * G4 + rowg);

    for (int t = 0; t < W; t++) {
        const int p = d ? (W - 1 - t) : t;
        const int buf = t & 1;
        const int nb = buf ^ 1;

        float xg_next = 0.0f;
        if (half == 0 && t + 1 < W) {
            int pn = d ? (W - 2 - t) : (t + 1);
            xg_next = __ldg(xgbase + (size_t)pn * G4 + rowg);
        }

        const float* hb = &h_sh[buf][half * 128];
        unsigned long long a01 = 0ull, a23 = 0ull;
#pragma unroll
        for (int i = 0; i < 128; i += 4) {
            ulonglong2 hp = *(const ulonglong2*)(hb + i);
            FMA_F32X2(a01, hp.x, wpk[(i >> 1) + 0]);
            FMA_F32X2(a23, hp.y, wpk[(i >> 1) + 1]);
        }
        float f0, f1, f2, f3;
        UNPACK_F32X2(f0, f1, a01);
        UNPACK_F32X2(f2, f3, a23);
        float s = (f0 + f1) + (f2 + f3);
        s += __shfl_xor_sync(0xFFFFFFFFu, s, 1);
        if (half == 0) gsh[r] = xg_cur + s;
        __syncthreads();

        float hn_out = 0.0f;
        if (tid < CELLS) {
            float gi = gsh[tid], gf = gsh[32 + tid], gg = gsh[64 + tid], go = gsh[96 + tid];
            float cn = fast_sigmoid(gf) * c + fast_sigmoid(gi) * fast_tanh(gg);
            c = cn;
            float hn = fast_sigmoid(go) * fast_tanh(cn);
            hn_out = hn;
            uint32_t laddr = smem_u32(&h_sh[nb][b * CELLS + tid]);
#pragma unroll
            for (int rk = 0; rk < CLUST; rk++) ST_CLUSTER_F32(laddr, rk, hn);
        }
        CLUSTER_ARRIVE();
        if (tid < CELLS)
            OUT[(size_t)p * HD + d * HH + b * CELLS + tid] = hn_out;
        CLUSTER_WAIT();

        xg_cur = xg_next;
    }
}

// ---------------- heads: logits + log_softmax ----------------
__global__ __launch_bounds__(128) void heads_kernel(
    const float* __restrict__ OUT,
    const float* __restrict__ Wp, const float* __restrict__ bp,
    const float* __restrict__ Wp2, const float* __restrict__ bp2,
    float* __restrict__ out)
{
    int w = blockIdx.x;
    __shared__ ALN float osh[HD];
    __shared__ ALN float lsh[T1 + T2];
    int tid = threadIdx.x;
    int lane = tid & 31, wid = tid >> 5;

    for (int kk = tid; kk < HD; kk += 128) osh[kk] = OUT[(size_t)w * HD + kk];
    __syncthreads();

    for (int l = wid; l < T1 + T2; l += 4) {
        const float* wr = (l < T1) ? (Wp + (size_t)l * HD) : (Wp2 + (size_t)(l - T1) * HD);
        float s = 0.0f;
#pragma unroll 4
        for (int kk = lane; kk < HD; kk += 32) s = fmaf(osh[kk], wr[kk], s);
#pragma unroll
        for (int o = 16; o; o >>= 1) s += __shfl_xor_sync(0xFFFFFFFFu, s, o);
        if (lane == 0) lsh[l] = s + ((l < T1) ? bp[l] : bp2[l - T1]);
    }
    __syncthreads();

    if (wid < 2) {
        int T = (wid == 0) ? T1 : T2;
        int base = (wid == 0) ? 0 : T1;
        float* ob = (wid == 0) ? (out + (size_t)w * T1)
                               : (out + (size_t)W * T1 + (size_t)w * T2);
        float mx = -1e30f;
        for (int l = lane; l < T; l += 32) mx = fmaxf(mx, lsh[base + l]);
#pragma unroll
        for (int o = 16; o; o >>= 1) mx = fmaxf(mx, __shfl_xor_sync(0xFFFFFFFFu, mx, o));
        float se = 0.0f;
        for (int l = lane; l < T; l += 32) se += expf(lsh[base + l] - mx);
#pragma unroll
        for (int o = 16; o; o >>= 1) se += __shfl_xor_sync(0xFFFFFFFFu, se, o);
        float lz = mx + logf(se);
        for (int l = lane; l < T; l += 32) ob[l] = lsh[base + l] - lz;
    }
}

// ---------------- host orchestration ----------------
static void* sym(const void* s) {
    void* p = nullptr;
    cudaGetSymbolAddress(&p, s);
    return p;
}

extern "C" void kernel_launch(void* const* d_in, const int* in_sizes, int n_in,
                              void* d_out, int out_size)
{
    const int*   wseq  = (const int*)d_in[0];
    const int*   cseq  = (const int*)d_in[1];
    const int*   lens  = (const int*)d_in[2];
    const float* cemb  = (const float*)d_in[3];
    const float* wemb  = (const float*)d_in[4];
    const float* cfWih = (const float*)d_in[5];
    const float* cfWhh = (const float*)d_in[6];
    const float* cfbih = (const float*)d_in[7];
    const float* cfbhh = (const float*)d_in[8];
    const float* cbWih = (const float*)d_in[9];
    const float* cbWhh = (const float*)d_in[10];
    const float* cbbih = (const float*)d_in[11];
    const float* cbbhh = (const float*)d_in[12];
    const float* wfWih = (const float*)d_in[13];
    const float* wfWhh = (const float*)d_in[14];
    const float* wfbih = (const float*)d_in[15];
    const float* wfbhh = (const float*)d_in[16];
    const float* wbWih = (const float*)d_in[17];
    const float* wbWhh = (const float*)d_in[18];
    const float* wbbih = (const float*)d_in[19];
    const float* wbbhh = (const float*)d_in[20];
    const float* Wp    = (const float*)d_in[21];
    const float* bp    = (const float*)d_in[22];
    const float* Wp2   = (const float*)d_in[23];
    const float* bp2   = (const float*)d_in[24];
    float* outp = (float*)d_out;

    float* Xc   = (float*)sym(g_Xc);
    float* XGf  = (float*)sym(g_XGf);
    float* XGb  = (float*)sym(g_XGb);
    float* Hst  = (float*)sym(g_Hst);
    float* Cst  = (float*)sym(g_Cst);
    float* WX   = (float*)sym(g_WX);
    float* XGw  = (float*)sym(g_XGw);
    float* OUT  = (float*)sym(g_OUT);
    float* WihC = (float*)sym(g_WihC);
    float* WhhC = (float*)sym(g_WhhC);
    float* WihW = (float*)sym(g_WihW);
    float* bias = (float*)sym(g_bias);

    const size_t HSZ = (size_t)W * HH;
    float* Hf0 = Hst + (0 * 2 + 0) * HSZ;   // [dir][parity]
    float* Hf1 = Hst + (0 * 2 + 1) * HSZ;
    float* Hb0 = Hst + (1 * 2 + 0) * HSZ;
    float* Hb1 = Hst + (1 * 2 + 1) * HSZ;
    float* Cf  = Cst + 0 * HSZ;
    float* Cb  = Cst + 1 * HSZ;

    cudaFuncSetAttribute(gemm_mma_dual_kernel, cudaFuncAttributeMaxDynamicSharedMemorySize,
                         GEMM_SMEM_BYTES);
    cudaFuncSetAttribute(gemm_lstm_fused_kernel, cudaFuncAttributeMaxDynamicSharedMemorySize,
                         GEMM_SMEM_BYTES);

    // ---- pack weights / biases ----
    pack_wihc_perm_kernel<<<G4, 128>>>(cfWih, WihC + 0 * (size_t)G4 * CDP);
    pack_wihc_perm_kernel<<<G4, 128>>>(cbWih, WihC + 1 * (size_t)G4 * CDP);
    pack_whhc_perm_kernel<<<G4, 256>>>(cfWhh, WhhC + 0 * (size_t)G4 * HH);
    pack_whhc_perm_kernel<<<G4, 256>>>(cbWhh, WhhC + 1 * (size_t)G4 * HH);
    pack_wihw_kernel<<<G4, 256>>>(wfWih, WihW + 0 * (size_t)G4 * WDINP);
    pack_wihw_kernel<<<G4, 256>>>(wbWih, WihW + 1 * (size_t)G4 * WDINP);
    bias_sum_perm_kernel<<<4, 256>>>(cfbih, cfbhh, bias + 0 * G4);
    bias_sum_perm_kernel<<<4, 256>>>(cbbih, cbbhh, bias + 1 * G4);
    bias_sum_kernel<<<4, 256>>>(wfbih, wfbhh, bias + 2 * G4);
    bias_sum_kernel<<<4, 256>>>(wbbih, wbbhh, bias + 3 * G4);

    // ---- gather char embeddings ----
    gather_char_kernel<<<LC * W, 128>>>(cseq, cemb, Xc);

    // ---- zero H parity-0 buffers + C state (6 * HSZ, contiguous layout) ----
    zero_kernel<<<(unsigned)((4 * HSZ + 255) / 256), 256>>>(Hst, 4 * HSZ);
    zero_kernel<<<(unsigned)((2 * HSZ + 255) / 256), 256>>>(Cst, 2 * HSZ);

    // ---- char input GEMM (permuted Wih/bias -> permuted XG cols) ----
    gemm_mma_dual_kernel<<<dim3(G4 / 128, (LC * W) / 128, 2), 256, GEMM_SMEM_BYTES>>>(
        Xc, Xc, WihC, WihC + (size_t)G4 * CDP, bias, bias + G4,
        nullptr, nullptr, XGf, XGb, G4, CDP);

    // ---- char BiLSTM: 16 fused recurrent GEMM+gate steps (both dirs per launch) ----
    for (int s = 0; s < LC; s++) {
        int tf = s, tb = LC - 1 - s;
        float* HinF  = (s & 1) ? Hf1 : Hf0;
        float* HoutF = (s & 1) ? Hf0 : Hf1;
        float* HinB  = (s & 1) ? Hb1 : Hb0;
        float* HoutB = (s & 1) ? Hb0 : Hb1;
        gemm_lstm_fused_kernel<<<dim3(G4 / 128, W / 128, 2), 256, GEMM_SMEM_BYTES>>>(
            HinF, HinB,
            WhhC, WhhC + (size_t)G4 * HH,
            XGf + (size_t)tf * W * G4, XGb + (size_t)tb * W * G4,
            HoutF, HoutB, Cf, Cb, lens, tf, tb);
    }
    // after 16 steps the final h lives in parity-0 buffers (Hf0 / Hb0)

    // ---- word-level input ----
    gather_word_kernel<<<W, 256>>>(wseq, wemb, Hf0, Hb0, WX);
    gemm_mma_dual_kernel<<<dim3(G4 / 128, W / 128, 2), 256, GEMM_SMEM_BYTES>>>(
        WX, WX, WihW, WihW + (size_t)G4 * WDINP, bias + 2 * G4, bias + 3 * G4,
        nullptr, nullptr, XGw, XGw + (size_t)W * G4, G4, WDINP);

    // ---- sequential word BiLSTM: 2 clusters of 8 CTAs, DSMEM exchange ----
    word_lstm_kernel<<<2 * CLUST, 256>>>(XGw, wfWhh, wbWhh, OUT);

    // ---- heads + log_softmax ----
    heads_kernel<<<W, 128>>>(OUT, Wp, bp, Wp2, bp2, outp);

    (void)in_sizes; (void)n_in; (void)out_size;
}